// round 4
// baseline (speedup 1.0000x reference)
#include <cuda_runtime.h>

#define BB 256
#define TT 1024
#define HH 64
#define GG 256   // 4*H gates

// Inter-layer activations (ping-pong). No allocs.
__device__ float g_bufA[BB * TT * HH];   // 64 MB
__device__ float g_bufB[BB * TT * HH];   // 64 MB

typedef unsigned long long ull;

__device__ __forceinline__ float sigf(float x) {
    x = fminf(fmaxf(x, -30.f), 30.f);
    return 1.0f / (1.0f + __expf(-x));
}
__device__ __forceinline__ float tanhf_fast(float x) {
    x = fminf(fmaxf(x, -15.f), 15.f);
    float e = __expf(-2.0f * x);
    return (1.0f - e) / (1.0f + e);
}

// Blackwell packed fp32 ops (PTX-only).
#define FFMA2(acc, a, b) \
    asm("fma.rn.f32x2 %0, %1, %2, %0;" : "+l"(acc) : "l"(a), "l"(b))
#define ADD2(d, a, b) \
    asm("add.rn.f32x2 %0, %1, %2;" : "=l"(d) : "l"(a), "l"(b))
#define UNPACK2(lo, hi, p) \
    asm("mov.b64 {%0,%1}, %2;" : "=f"(lo), "=f"(hi) : "l"(p))
#define PACK2(p, lo, hi) \
    asm("mov.b64 %0, {%1,%2};" : "=l"(p) : "f"(lo), "f"(hi))

// ---------------------------------------------------------------------------
// Fused warp-specialized LSTM layer.
// 128 CTAs x 512 threads (1 CTA/SM). CTA owns batch rows {2b, 2b+1}.
//   threads   0..255 : consumers — gate row g; W_hh row in regs; recurrence.
//   threads 256..511 : producers — gate row g; W_ih row in regs; compute
//                      gx[t] = b_ih+b_hh + W_ih·x_t into a 4-slot smem ring,
//                      running 2 steps ahead of the consumers.
// Sync: consumers use a private named barrier between gate and update phases;
// one CTA-wide __syncthreads per step advances the rings.
// ---------------------------------------------------------------------------
template <bool FIRST>
__global__ void __launch_bounds__(512, 1)
lstm_fused(const float* __restrict__ xin,   // FIRST: [B,T] else [B,T,64]
           const float* __restrict__ wih,   // FIRST: [256] else [256,64]
           const float* __restrict__ whh,   // [256,64]
           const float* __restrict__ bih,   // [256]
           const float* __restrict__ bhh,   // [256]
           float* __restrict__ hout)        // [B,T,64]
{
    const int tid = threadIdx.x;
    const int cb0 = blockIdx.x * 2;

    __shared__ __align__(16) float hs[2][64];
    __shared__ float gsm[2][256];
    __shared__ __align__(16) float gring[4][2][256];  // gx ring, 8 KB
    __shared__ __align__(16) float xring[4][2][64];   // x  ring, 2 KB

    if (tid < 256) {
        // ================= consumer =================
        const int g = tid;
        ull whh2[32];
        {
            const ull* wr = reinterpret_cast<const ull*>(whh + g * 64);
            #pragma unroll
            for (int k = 0; k < 32; k++) whh2[k] = wr[k];
        }
        if (g < 128) hs[g >> 6][g & 63] = 0.f;
        float c = 0.f;
        __syncthreads();   // matches producer barrier A (x staged)
        __syncthreads();   // matches producer barrier B (gring[0..1] ready)

        for (int t = 0; t < TT; ++t) {
            // h-part: 2 batches x 4 chains (depth 8), broadcast LDS.128
            ull p0 = 0, p1 = 0, p2 = 0, p3 = 0;
            ull q0 = 0, q1 = 0, q2 = 0, q3 = 0;
            const ulonglong2* h0 = reinterpret_cast<const ulonglong2*>(hs[0]);
            const ulonglong2* h1 = reinterpret_cast<const ulonglong2*>(hs[1]);
            #pragma unroll
            for (int k = 0; k < 8; k++) {
                ulonglong2 va = h0[2 * k];
                ulonglong2 vb = h0[2 * k + 1];
                ulonglong2 vc = h1[2 * k];
                ulonglong2 vd = h1[2 * k + 1];
                FFMA2(p0, whh2[4 * k],     va.x);
                FFMA2(p1, whh2[4 * k + 1], va.y);
                FFMA2(p2, whh2[4 * k + 2], vb.x);
                FFMA2(p3, whh2[4 * k + 3], vb.y);
                FFMA2(q0, whh2[4 * k],     vc.x);
                FFMA2(q1, whh2[4 * k + 1], vc.y);
                FFMA2(q2, whh2[4 * k + 2], vd.x);
                FFMA2(q3, whh2[4 * k + 3], vd.y);
            }
            ull u, v; float lo, hi;
            ADD2(u, p0, p1); ADD2(v, p2, p3); ADD2(u, u, v); UNPACK2(lo, hi, u);
            float a0 = lo + hi + gring[t & 3][0][g];
            ADD2(u, q0, q1); ADD2(v, q2, q3); ADD2(u, u, v); UNPACK2(lo, hi, u);
            float a1 = lo + hi + gring[t & 3][1][g];

            // gate rows: [0,64) i  [64,128) f  [128,192) g(tanh)  [192,256) o
            float v0, v1;
            if (g >= 128 && g < 192) { v0 = tanhf_fast(a0); v1 = tanhf_fast(a1); }
            else                     { v0 = sigf(a0);       v1 = sigf(a1); }
            gsm[0][g] = v0;
            gsm[1][g] = v1;
            asm volatile("bar.sync 1, 256;" ::: "memory");  // consumers only

            if (g < 128) {
                int b = g >> 6, j = g & 63;
                float iv = gsm[b][j];
                float fv = gsm[b][64 + j];
                float gv = gsm[b][128 + j];
                float ov = gsm[b][192 + j];
                c = fv * c + iv * gv;
                float hval = ov * tanhf_fast(c);
                hs[b][j] = hval;
                hout[(((size_t)(cb0 + b)) * TT + t) * 64 + j] = hval;
            }
            __syncthreads();
        }
    } else {
        // ================= producer =================
        const int g = tid - 256;
        ull wih2[32];
        float wscal = 0.f;
        if (FIRST) {
            wscal = wih[g];
        } else {
            const ull* wr = reinterpret_cast<const ull*>(wih + g * 64);
            #pragma unroll
            for (int k = 0; k < 32; k++) wih2[k] = wr[k];
        }
        const float bsum = bih[g] + bhh[g];

#define PRODUCE(SLOT)                                                        \
    do {                                                                     \
        if (FIRST) {                                                         \
            gring[SLOT][0][g] = bsum + wscal * xring[SLOT][0][0];            \
            gring[SLOT][1][g] = bsum + wscal * xring[SLOT][1][0];            \
        } else {                                                             \
            ull xa0 = 0, xa1 = 0, xb0 = 0, xb1 = 0;                          \
            const ulonglong2* x0 =                                           \
                reinterpret_cast<const ulonglong2*>(xring[SLOT][0]);         \
            const ulonglong2* x1 =                                           \
                reinterpret_cast<const ulonglong2*>(xring[SLOT][1]);         \
            _Pragma("unroll")                                                \
            for (int k = 0; k < 16; k++) {                                   \
                ulonglong2 va = x0[k];                                       \
                ulonglong2 vb = x1[k];                                       \
                FFMA2(xa0, wih2[2 * k],     va.x);                           \
                FFMA2(xa1, wih2[2 * k + 1], va.y);                           \
                FFMA2(xb0, wih2[2 * k],     vb.x);                           \
                FFMA2(xb1, wih2[2 * k + 1], vb.y);                           \
            }                                                                \
            float lo, hi;                                                    \
            ADD2(xa0, xa0, xa1); UNPACK2(lo, hi, xa0);                       \
            gring[SLOT][0][g] = bsum + lo + hi;                              \
            ADD2(xb0, xb0, xb1); UNPACK2(lo, hi, xb0);                       \
            gring[SLOT][1][g] = bsum + lo + hi;                              \
        }                                                                    \
    } while (0)

        // prologue: stage x for steps 0..2, then produce gx[0], gx[1]
        if (FIRST) {
            if (g < 2) {
                #pragma unroll
                for (int s = 0; s < 3; s++)
                    xring[s][g][0] = xin[(cb0 + g) * TT + s];
            }
        } else {
            if (g < 128) {
                int b = g >> 6, j = g & 63;
                #pragma unroll
                for (int s = 0; s < 3; s++)
                    xring[s][b][j] = xin[((size_t)(cb0 + b) * TT + s) * 64 + j];
            }
        }
        __syncthreads();   // A
        PRODUCE(0);
        PRODUCE(1);
        __syncthreads();   // B

        for (int t = 0; t < TT; ++t) {
            // stage x for step t+3 (read next interval)
            int ts = t + 3;
            if (ts < TT) {
                if (FIRST) {
                    if (g < 2) xring[ts & 3][g][0] = xin[(cb0 + g) * TT + ts];
                } else if (g < 128) {
                    int b = g >> 6, j = g & 63;
                    xring[ts & 3][b][j] =
                        xin[((size_t)(cb0 + b) * TT + ts) * 64 + j];
                }
            }
            // produce gx for step t+2 (consumed 2 intervals from now)
            int tc = t + 2;
            if (tc < TT) {
                int sl = tc & 3;
                PRODUCE(sl);
            }
            __syncthreads();
        }
#undef PRODUCE
    }
}

// ---------------------------------------------------------------------------
// Head: out = relu(relu(h) @ W1^T + b1) @ W2^T + b2 (packed FFMA2).
// ---------------------------------------------------------------------------
__global__ void __launch_bounds__(256)
fc_kernel(const float* __restrict__ hin,  // [B,T,64]
          const float* __restrict__ W1,   // [64,64]
          const float* __restrict__ b1,   // [64]
          const float* __restrict__ W2,   // [1,64]
          const float* __restrict__ b2,   // [1]
          float* __restrict__ out)        // [B*T]
{
    __shared__ ull  W1P[64 * 32];   // (W1[l][k], W1[l+32][k])
    __shared__ float b1s[64];
    __shared__ float w2s[64];
    __shared__ float hsm[8][2][64];

    for (int i = threadIdx.x; i < 64 * 32; i += 256) {
        int k = i >> 5, l = i & 31;
        ull p; PACK2(p, W1[l * 64 + k], W1[(l + 32) * 64 + k]);
        W1P[k * 32 + l] = p;
    }
    if (threadIdx.x < 64) {
        b1s[threadIdx.x] = b1[threadIdx.x];
        w2s[threadIdx.x] = W2[threadIdx.x];
    }
    __syncthreads();
    const float b2v = b2[0];

    const int warp = threadIdx.x >> 5, lane = threadIdx.x & 31;
    ull ybias; PACK2(ybias, b1s[lane], b1s[lane + 32]);
    const float w2lo = w2s[lane], w2hi = w2s[lane + 32];

    const int npairs = BB * TT / 2;
    for (int pair = blockIdx.x * 8 + warp; pair < npairs; pair += gridDim.x * 8) {
        size_t p0 = (size_t)pair * 2;
        float h00 = fmaxf(hin[p0 * 64 + lane], 0.f);
        float h01 = fmaxf(hin[p0 * 64 + 32 + lane], 0.f);
        float h10 = fmaxf(hin[(p0 + 1) * 64 + lane], 0.f);
        float h11 = fmaxf(hin[(p0 + 1) * 64 + 32 + lane], 0.f);
        hsm[warp][0][lane]      = h00;
        hsm[warp][0][lane + 32] = h01;
        hsm[warp][1][lane]      = h10;
        hsm[warp][1][lane + 32] = h11;
        __syncwarp();

        ull y0a = ybias, y0b = 0, y1a = ybias, y1b = 0;
        #pragma unroll
        for (int k = 0; k < 64; k += 2) {
            ull w0 = W1P[k * 32 + lane];
            ull w1 = W1P[(k + 1) * 32 + lane];
            float hv00 = hsm[warp][0][k], hv01 = hsm[warp][0][k + 1];
            float hv10 = hsm[warp][1][k], hv11 = hsm[warp][1][k + 1];
            ull d00; PACK2(d00, hv00, hv00);
            ull d01; PACK2(d01, hv01, hv01);
            ull d10; PACK2(d10, hv10, hv10);
            ull d11; PACK2(d11, hv11, hv11);
            FFMA2(y0a, w0, d00);
            FFMA2(y0b, w1, d01);
            FFMA2(y1a, w0, d10);
            FFMA2(y1b, w1, d11);
        }
        ADD2(y0a, y0a, y0b);
        ADD2(y1a, y1a, y1b);
        float u0, u1, v0, v1;
        UNPACK2(u0, u1, y0a);
        UNPACK2(v0, v1, y1a);
        float part0 = fmaxf(u0, 0.f) * w2lo + fmaxf(u1, 0.f) * w2hi;
        float part1 = fmaxf(v0, 0.f) * w2lo + fmaxf(v1, 0.f) * w2hi;
        ull pp; PACK2(pp, part0, part1);
        #pragma unroll
        for (int off = 16; off; off >>= 1) {
            ull o = __shfl_down_sync(0xffffffffu, pp, off);
            ADD2(pp, pp, o);
        }
        if (lane == 0) {
            UNPACK2(part0, part1, pp);
            reinterpret_cast<float2*>(out)[pair] =
                make_float2(part0 + b2v, part1 + b2v);
        }
        __syncwarp();
    }
}

extern "C" void kernel_launch(void* const* d_in, const int* in_sizes, int n_in,
                              void* d_out, int out_size)
{
    const float* x    = (const float*)d_in[0];  // [256,1024,1]
    const float* wih0 = (const float*)d_in[1];  // [256,1]
    const float* wihR = (const float*)d_in[2];  // [4,256,64]
    const float* whh  = (const float*)d_in[3];  // [5,256,64]
    const float* bih  = (const float*)d_in[4];  // [5,256]
    const float* bhh  = (const float*)d_in[5];  // [5,256]
    const float* W1   = (const float*)d_in[6];  // [64,64]
    const float* b1   = (const float*)d_in[7];  // [64]
    const float* W2   = (const float*)d_in[8];  // [1,64]
    const float* b2   = (const float*)d_in[9];  // [1]
    float* out = (float*)d_out;                 // [256,1024,1]
    (void)in_sizes; (void)n_in; (void)out_size; // future == 0 per setup

    void *pA = nullptr, *pB = nullptr;
    cudaGetSymbolAddress(&pA, g_bufA);
    cudaGetSymbolAddress(&pB, g_bufB);
    float* bufA = (float*)pA;
    float* bufB = (float*)pB;

    const int WSZ = GG * HH;  // per-layer weight block

    lstm_fused<true><<<128, 512>>>(x, wih0, whh, bih, bhh, bufA);
    float* cur = bufA;
    float* nxt = bufB;
    for (int l = 1; l < 5; ++l) {
        lstm_fused<false><<<128, 512>>>(cur, wihR + (l - 1) * WSZ,
                                        whh + l * WSZ,
                                        bih + l * GG, bhh + l * GG, nxt);
        float* tmp = cur; cur = nxt; nxt = tmp;
    }
    fc_kernel<<<2048, 256>>>(cur, W1, b1, W2, b2, out);
}

// round 5
// speedup vs baseline: 1.1210x; 1.1210x over previous
#include <cuda_runtime.h>

#define BB 256
#define TT 1024
#define HH 64
#define GG 256   // 4*H gates

#define L0_CTAS 16
#define L0_ROWS 16
#define LN_CTAS 32
#define LN_ROWS 8
#define NLAYERS 5
#define GRID_WF (L0_CTAS + 4 * LN_CTAS)   // 144 <= 148 SMs -> all co-resident
#define WSZ (GG * HH)

// Per-layer hidden-state buffers (5 x 64 MB) + progress flags. No allocs.
__device__ float g_h[NLAYERS][BB * TT * HH];
__device__ int   g_flags[NLAYERS][LN_CTAS];

typedef unsigned long long ull;

__device__ __forceinline__ float sigf(float x) {
    x = fminf(fmaxf(x, -30.f), 30.f);
    float e = __expf(-x);
    return __fdividef(1.0f, 1.0f + e);
}
__device__ __forceinline__ float tanhf_fast(float x) {
    x = fminf(fmaxf(x, -15.f), 15.f);
    float e = __expf(-2.0f * x);
    return __fdividef(1.0f - e, 1.0f + e);
}

// Blackwell packed fp32 ops (PTX-only).
#define FFMA2(acc, a, b) \
    asm("fma.rn.f32x2 %0, %1, %2, %0;" : "+l"(acc) : "l"(a), "l"(b))
#define ADD2(d, a, b) \
    asm("add.rn.f32x2 %0, %1, %2;" : "=l"(d) : "l"(a), "l"(b))
#define UNPACK2(lo, hi, p) \
    asm("mov.b64 {%0,%1}, %2;" : "=f"(lo), "=f"(hi) : "l"(p))
#define PACK2(p, lo, hi) \
    asm("mov.b64 %0, {%1,%2};" : "=l"(p) : "f"(lo), "f"(hi))

__device__ __forceinline__ int ld_acquire(const int* p) {
    int v;
    asm volatile("ld.global.acquire.gpu.b32 %0, [%1];" : "=r"(v) : "l"(p) : "memory");
    return v;
}
__device__ __forceinline__ void st_release(int* p, int v) {
    asm volatile("st.global.release.gpu.b32 [%0], %1;" :: "l"(p), "r"(v) : "memory");
}

__global__ void reset_flags() {
    int i = threadIdx.x;
    if (i < NLAYERS * LN_CTAS) ((int*)g_flags)[i] = 0;
}

// ---------------------------------------------------------------------------
// Wavefront kernel: all 5 LSTM layers concurrently, skewed in time.
//   bid <  16             : layer 0, 16 batch rows   (x is scalar/step)
//   bid >= 16             : layer 1+ (li = (bid-16)/32), 8 batch rows
// Thread g owns gate row g: W_hh row (+ W_ih row for l>=1) in registers.
// h handoff: global g_h[l] + monotonic flags (release/acquire), consumer lags
// ~4 steps so h_prev loads are latency-hidden.
// ---------------------------------------------------------------------------
__global__ void __launch_bounds__(256, 1)
wavefront(const float* __restrict__ x,     // [B,T]
          const float* __restrict__ wih0,  // [256]
          const float* __restrict__ wihR,  // [4,256,64]
          const float* __restrict__ whh,   // [5,256,64]
          const float* __restrict__ bih,   // [5,256]
          const float* __restrict__ bhh)   // [5,256]
{
    __shared__ __align__(16) float hs[L0_ROWS][64];      // own h state
    __shared__ float gsm[L0_ROWS][GG];                   // gate values
    __shared__ __align__(16) float xr[4][LN_ROWS][64];   // h_prev ring (l>=1)
    __shared__ float xs0[4][L0_ROWS];                    // x ring (layer 0)

    const int tid = threadIdx.x;
    const int bid = blockIdx.x;

    if (bid < L0_CTAS) {
        // ============================ layer 0 ============================
        const int r0 = bid * L0_ROWS;
        ull whh2[32];
        {
            const ull* wr = reinterpret_cast<const ull*>(whh + tid * 64);
            #pragma unroll
            for (int k = 0; k < 32; k++) whh2[k] = wr[k];
        }
        const float wsc  = wih0[tid];
        const float bsum = bih[tid] + bhh[tid];

        #pragma unroll
        for (int i = 0; i < 4; i++) {
            int v = tid + 256 * i;
            hs[v >> 6][v & 63] = 0.f;
        }
        float c0 = 0.f, c1 = 0.f, c2 = 0.f, c3 = 0.f;

        float q = 0.f;
        if (tid < L0_ROWS) {
            const float* xp = x + (size_t)(r0 + tid) * TT;
            xs0[0][tid] = xp[0];
            xs0[1][tid] = xp[1];
            q = xp[2];
        }
        __syncthreads();

        int* myflag = &g_flags[0][bid];
        for (int t = 0; t < TT; ++t) {
            // ---- phase A: gates for 16 rows ----
            #pragma unroll
            for (int r = 0; r < L0_ROWS; ++r) {
                const ulonglong2* hp = reinterpret_cast<const ulonglong2*>(hs[r]);
                ull a0 = 0, a1 = 0, a2 = 0, a3 = 0;
                #pragma unroll
                for (int k = 0; k < 8; k++) {
                    ulonglong2 v1 = hp[2 * k];
                    ulonglong2 v2 = hp[2 * k + 1];
                    FFMA2(a0, whh2[4 * k],     v1.x);
                    FFMA2(a1, whh2[4 * k + 1], v1.y);
                    FFMA2(a2, whh2[4 * k + 2], v2.x);
                    FFMA2(a3, whh2[4 * k + 3], v2.y);
                }
                ull u, v; ADD2(u, a0, a1); ADD2(v, a2, a3); ADD2(u, u, v);
                float lo, hi; UNPACK2(lo, hi, u);
                float a = lo + hi + bsum + wsc * xs0[t & 3][r];
                float val = (tid >= 128 && tid < 192) ? tanhf_fast(a) : sigf(a);
                gsm[r][tid] = val;
            }
            __syncthreads();
            // ---- phase B: state update (4 values/thread) ----
            #pragma unroll
            for (int i = 0; i < 4; i++) {
                int v = tid + 256 * i;
                int r = v >> 6, j = v & 63;
                float iv = gsm[r][j];
                float fv = gsm[r][64 + j];
                float gv = gsm[r][128 + j];
                float ov = gsm[r][192 + j];
                float c = (i == 0) ? c0 : (i == 1) ? c1 : (i == 2) ? c2 : c3;
                c = fv * c + iv * gv;
                if (i == 0) c0 = c; else if (i == 1) c1 = c;
                else if (i == 2) c2 = c; else c3 = c;
                float hval = ov * tanhf_fast(c);
                hs[r][j] = hval;
                g_h[0][((size_t)(r0 + r) * TT + t) * 64 + j] = hval;
            }
            if (tid < L0_ROWS) {
                if (t + 2 < TT) xs0[(t + 2) & 3][tid] = q;
                if (t + 3 < TT) q = x[(size_t)(r0 + tid) * TT + (t + 3)];
            }
            bool publish = ((t & 1) == 1) || (t == TT - 1);
            if (publish) __threadfence();
            __syncthreads();
            if (publish && tid == 0) st_release(myflag, t + 1);
        }
    } else {
        // ============================ layers 1..4 ============================
        const int li    = (bid - L0_CTAS) >> 5;   // 0..3
        const int l     = li + 1;
        const int chunk = (bid - L0_CTAS) & 31;
        const int r0    = chunk * LN_ROWS;

        ull whh2[32], wih2[32];
        {
            const ull* wr = reinterpret_cast<const ull*>(whh + l * WSZ + tid * 64);
            #pragma unroll
            for (int k = 0; k < 32; k++) whh2[k] = wr[k];
            const ull* wi = reinterpret_cast<const ull*>(wihR + li * WSZ + tid * 64);
            #pragma unroll
            for (int k = 0; k < 32; k++) wih2[k] = wi[k];
        }
        const float bsum = bih[l * GG + tid] + bhh[l * GG + tid];

        #pragma unroll
        for (int i = 0; i < 2; i++) {
            int v = tid + 256 * i;
            hs[v >> 6][v & 63] = 0.f;
        }
        float c0 = 0.f, c1 = 0.f;

        const int* prod = &g_flags[l - 1][(l == 1) ? (chunk >> 1) : chunk];
        int* myflag = &g_flags[l][chunk];
        const float* hprev = g_h[l - 1];

        // per-thread staging coordinates (2 values/thread)
        const int rA = tid >> 6,        jA = tid & 63;        // value tid
        const int rB = 4 + (tid >> 6),  jB = tid & 63;        // value tid+256
        const size_t baseA = (size_t)(r0 + rA) * TT * 64 + jA;
        const size_t baseB = (size_t)(r0 + rB) * TT * 64 + jB;

        // prologue: stage h_prev[0..1], prefetch h_prev[2]
        while (ld_acquire(prod) < 2) __nanosleep(128);
        #pragma unroll
        for (int s = 0; s < 2; s++) {
            xr[s][rA][jA] = __ldcg(hprev + baseA + (size_t)s * 64);
            xr[s][rB][jB] = __ldcg(hprev + baseB + (size_t)s * 64);
        }
        while (ld_acquire(prod) < 3) __nanosleep(128);
        float qA = __ldcg(hprev + baseA + 2 * 64);
        float qB = __ldcg(hprev + baseB + 2 * 64);
        __syncthreads();

        for (int t = 0; t < TT; ++t) {
            // early flag sample (consumed in phase B; hides acquire latency)
            int fl = (t + 3 < TT) ? ld_acquire(prod) : 0x7fffffff;

            // ---- phase A: gates for 8 rows (h-part + x-part) ----
            #pragma unroll
            for (int r = 0; r < LN_ROWS; ++r) {
                const ulonglong2* hp = reinterpret_cast<const ulonglong2*>(hs[r]);
                const ulonglong2* xp = reinterpret_cast<const ulonglong2*>(xr[t & 3][r]);
                ull a0 = 0, a1 = 0, a2 = 0, a3 = 0;
                #pragma unroll
                for (int k = 0; k < 8; k++) {
                    ulonglong2 v1 = hp[2 * k];
                    ulonglong2 v2 = hp[2 * k + 1];
                    ulonglong2 w1 = xp[2 * k];
                    ulonglong2 w2 = xp[2 * k + 1];
                    FFMA2(a0, whh2[4 * k],     v1.x);
                    FFMA2(a1, whh2[4 * k + 1], v1.y);
                    FFMA2(a2, whh2[4 * k + 2], v2.x);
                    FFMA2(a3, whh2[4 * k + 3], v2.y);
                    FFMA2(a0, wih2[4 * k],     w1.x);
                    FFMA2(a1, wih2[4 * k + 1], w1.y);
                    FFMA2(a2, wih2[4 * k + 2], w2.x);
                    FFMA2(a3, wih2[4 * k + 3], w2.y);
                }
                ull u, v; ADD2(u, a0, a1); ADD2(v, a2, a3); ADD2(u, u, v);
                float lo, hi; UNPACK2(lo, hi, u);
                float a = lo + hi + bsum;
                float val = (tid >= 128 && tid < 192) ? tanhf_fast(a) : sigf(a);
                gsm[r][tid] = val;
            }
            __syncthreads();
            // ---- phase B: update (2 values/thread) + h_prev pipeline ----
            {
                float iv = gsm[rA][jA];
                float fv = gsm[rA][64 + jA];
                float gv = gsm[rA][128 + jA];
                float ov = gsm[rA][192 + jA];
                c0 = fv * c0 + iv * gv;
                float hval = ov * tanhf_fast(c0);
                hs[rA][jA] = hval;
                g_h[l][baseA + (size_t)t * 64] = hval;
            }
            {
                float iv = gsm[rB][jB];
                float fv = gsm[rB][64 + jB];
                float gv = gsm[rB][128 + jB];
                float ov = gsm[rB][192 + jB];
                c1 = fv * c1 + iv * gv;
                float hval = ov * tanhf_fast(c1);
                hs[rB][jB] = hval;
                g_h[l][baseB + (size_t)t * 64] = hval;
            }
            if (t + 2 < TT) {
                xr[(t + 2) & 3][rA][jA] = qA;
                xr[(t + 2) & 3][rB][jB] = qB;
            }
            if (t + 3 < TT) {
                int tgt = (t + 4 < TT) ? (t + 4) : TT;
                while (fl < tgt) { __nanosleep(128); fl = ld_acquire(prod); }
                qA = __ldcg(hprev + baseA + (size_t)(t + 3) * 64);
                qB = __ldcg(hprev + baseB + (size_t)(t + 3) * 64);
            }
            bool publish = (((t & 1) == 1) || (t == TT - 1)) && (l < 4);
            if (publish) __threadfence();
            __syncthreads();
            if (publish && tid == 0) st_release(myflag, t + 1);
        }
    }
}

// ---------------------------------------------------------------------------
// Head: out = relu(relu(h) @ W1^T + b1) @ W2^T + b2 (packed FFMA2).
// ---------------------------------------------------------------------------
__global__ void __launch_bounds__(256)
fc_kernel(const float* __restrict__ hin,  // [B,T,64]
          const float* __restrict__ W1,   // [64,64]
          const float* __restrict__ b1,   // [64]
          const float* __restrict__ W2,   // [1,64]
          const float* __restrict__ b2,   // [1]
          float* __restrict__ out)        // [B*T]
{
    __shared__ ull  W1P[64 * 32];
    __shared__ float b1s[64];
    __shared__ float w2s[64];
    __shared__ float hsm[8][2][64];

    for (int i = threadIdx.x; i < 64 * 32; i += 256) {
        int k = i >> 5, l = i & 31;
        ull p; PACK2(p, W1[l * 64 + k], W1[(l + 32) * 64 + k]);
        W1P[k * 32 + l] = p;
    }
    if (threadIdx.x < 64) {
        b1s[threadIdx.x] = b1[threadIdx.x];
        w2s[threadIdx.x] = W2[threadIdx.x];
    }
    __syncthreads();
    const float b2v = b2[0];

    const int warp = threadIdx.x >> 5, lane = threadIdx.x & 31;
    ull ybias; PACK2(ybias, b1s[lane], b1s[lane + 32]);
    const float w2lo = w2s[lane], w2hi = w2s[lane + 32];

    const int npairs = BB * TT / 2;
    for (int pair = blockIdx.x * 8 + warp; pair < npairs; pair += gridDim.x * 8) {
        size_t p0 = (size_t)pair * 2;
        float h00 = fmaxf(hin[p0 * 64 + lane], 0.f);
        float h01 = fmaxf(hin[p0 * 64 + 32 + lane], 0.f);
        float h10 = fmaxf(hin[(p0 + 1) * 64 + lane], 0.f);
        float h11 = fmaxf(hin[(p0 + 1) * 64 + 32 + lane], 0.f);
        hsm[warp][0][lane]      = h00;
        hsm[warp][0][lane + 32] = h01;
        hsm[warp][1][lane]      = h10;
        hsm[warp][1][lane + 32] = h11;
        __syncwarp();

        ull y0a = ybias, y0b = 0, y1a = ybias, y1b = 0;
        #pragma unroll
        for (int k = 0; k < 64; k += 2) {
            ull w0 = W1P[k * 32 + lane];
            ull w1 = W1P[(k + 1) * 32 + lane];
            float hv00 = hsm[warp][0][k], hv01 = hsm[warp][0][k + 1];
            float hv10 = hsm[warp][1][k], hv11 = hsm[warp][1][k + 1];
            ull d00; PACK2(d00, hv00, hv00);
            ull d01; PACK2(d01, hv01, hv01);
            ull d10; PACK2(d10, hv10, hv10);
            ull d11; PACK2(d11, hv11, hv11);
            FFMA2(y0a, w0, d00);
            FFMA2(y0b, w1, d01);
            FFMA2(y1a, w0, d10);
            FFMA2(y1b, w1, d11);
        }
        ADD2(y0a, y0a, y0b);
        ADD2(y1a, y1a, y1b);
        float u0, u1, v0, v1;
        UNPACK2(u0, u1, y0a);
        UNPACK2(v0, v1, y1a);
        float part0 = fmaxf(u0, 0.f) * w2lo + fmaxf(u1, 0.f) * w2hi;
        float part1 = fmaxf(v0, 0.f) * w2lo + fmaxf(v1, 0.f) * w2hi;
        ull pp; PACK2(pp, part0, part1);
        #pragma unroll
        for (int off = 16; off; off >>= 1) {
            ull o = __shfl_down_sync(0xffffffffu, pp, off);
            ADD2(pp, pp, o);
        }
        if (lane == 0) {
            UNPACK2(part0, part1, pp);
            reinterpret_cast<float2*>(out)[pair] =
                make_float2(part0 + b2v, part1 + b2v);
        }
        __syncwarp();
    }
}

extern "C" void kernel_launch(void* const* d_in, const int* in_sizes, int n_in,
                              void* d_out, int out_size)
{
    const float* x    = (const float*)d_in[0];  // [256,1024,1]
    const float* wih0 = (const float*)d_in[1];  // [256,1]
    const float* wihR = (const float*)d_in[2];  // [4,256,64]
    const float* whh  = (const float*)d_in[3];  // [5,256,64]
    const float* bih  = (const float*)d_in[4];  // [5,256]
    const float* bhh  = (const float*)d_in[5];  // [5,256]
    const float* W1   = (const float*)d_in[6];  // [64,64]
    const float* b1   = (const float*)d_in[7];  // [64]
    const float* W2   = (const float*)d_in[8];  // [1,64]
    const float* b2   = (const float*)d_in[9];  // [1]
    float* out = (float*)d_out;                 // [256,1024,1]
    (void)in_sizes; (void)n_in; (void)out_size; // future == 0 per setup

    void* pH = nullptr;
    cudaGetSymbolAddress(&pH, g_h);
    float* h4 = (float*)pH + 4 * (size_t)BB * TT * HH;

    reset_flags<<<1, 256>>>();
    wavefront<<<GRID_WF, 256>>>(x, wih0, wihR, whh, bih, bhh);
    fc_kernel<<<2048, 256>>>(h4, W1, b1, W2, b2, out);
}